// round 3
// baseline (speedup 1.0000x reference)
#include <cuda_runtime.h>
#include <cstdint>

#define FM 0xFFFFFFFFu

constexpr int NUSERS = 100000;
constexpr int NITEMS = 50000;
constexpr int NNODES = NUSERS + NITEMS;   // 150000
constexpr int NNZV   = 2000000;
constexpr int EMBV   = 100;
constexpr int BATCHV = 16384;
constexpr int V4     = EMBV / 4;          // 25 float4 per row
constexpr int STILE  = 1024;
constexpr int NBLK1  = (NNODES + STILE - 1) / STILE; // 147 (<= 148 SMs: wave-1 resident)

// ---- scratch (static device arrays; no runtime allocation) ----
__device__ int    g_cntchain[NNODES + 256];          // [0..NNODES)=cnt, [NNODES..)=chain
__device__ int    g_rp[NNODES + 1];
__device__ int    g_cur[NNODES];
__device__ __align__(16) int2 g_edge[NNZV];          // {col, val_bits}, CSR-ordered
__device__ float4 g_e1[(size_t)NNODES * V4];         // layer-1 output, 60 MB

// ================= histogram (vectorized: 4 edges/thread) =================

__global__ void k_hist(const int* __restrict__ row) {
    int t = blockIdx.x * blockDim.x + threadIdx.x;
    int e = t * 4;
    if (e + 3 < NNZV) {
        int4 r = *(const int4*)&row[e];
        atomicAdd(&g_cntchain[r.x], 1);
        atomicAdd(&g_cntchain[r.y], 1);
        atomicAdd(&g_cntchain[r.z], 1);
        atomicAdd(&g_cntchain[r.w], 1);
    } else {
        for (int k = e; k < NNZV; k++) atomicAdd(&g_cntchain[row[k]], 1);
    }
}

// ====== fused scan: counts -> rowptr + cursor, single kernel (chained) ======

__global__ void k_scan_fused() {
    __shared__ int sm[STILE];
    __shared__ int sPrev;
    int i = blockIdx.x * STILE + threadIdx.x;
    int v = (i < NNODES) ? g_cntchain[i] : 0;
    sm[threadIdx.x] = v;
    __syncthreads();
    for (int off = 1; off < STILE; off <<= 1) {
        int t = (threadIdx.x >= off) ? sm[threadIdx.x - off] : 0;
        __syncthreads();
        sm[threadIdx.x] += t;
        __syncthreads();
    }
    // chained prefix across blocks (all 147 blocks are wave-1 resident)
    if (threadIdx.x == 0) {
        int prev = 0;
        if (blockIdx.x > 0) {
            int* pc = &g_cntchain[NNODES + blockIdx.x - 1];
            int pv = atomicAdd(pc, 0);
            while (pv == 0) {
                __nanosleep(64);
                pv = atomicAdd(pc, 0);
            }
            prev = pv - 1;
        }
        atomicExch(&g_cntchain[NNODES + blockIdx.x], prev + sm[STILE - 1] + 1);
        sPrev = prev;
    }
    __syncthreads();
    if (i < NNODES) {
        int incl = sPrev + sm[threadIdx.x];
        g_rp[i + 1] = incl;
        g_cur[i]    = incl - v;
        if (i == 0) g_rp[0] = 0;
    }
}

// ================= scatter into CSR order (4 edges/thread) =================

__global__ void k_scatter(const int* __restrict__ row, const int* __restrict__ col,
                          const float* __restrict__ val) {
    int t = blockIdx.x * blockDim.x + threadIdx.x;
    int e = t * 4;
    if (e + 3 < NNZV) {
        int4   r = *(const int4*)&row[e];
        int4   c = *(const int4*)&col[e];
        float4 v = *(const float4*)&val[e];
        int p0 = atomicAdd(&g_cur[r.x], 1); g_edge[p0] = make_int2(c.x, __float_as_int(v.x));
        int p1 = atomicAdd(&g_cur[r.y], 1); g_edge[p1] = make_int2(c.y, __float_as_int(v.y));
        int p2 = atomicAdd(&g_cur[r.z], 1); g_edge[p2] = make_int2(c.z, __float_as_int(v.z));
        int p3 = atomicAdd(&g_cur[r.w], 1); g_edge[p3] = make_int2(c.w, __float_as_int(v.w));
    } else {
        for (int k = e; k < NNZV; k++) {
            int p = atomicAdd(&g_cur[row[k]], 1);
            g_edge[p] = make_int2(col[k], __float_as_int(val[k]));
        }
    }
}

// ================= Layer 1: e1 = A @ ego (full, warp-per-row) =================

__device__ __forceinline__ const float4* feat_ptr(int c, const float4* ue4, const float4* ie4) {
    return (c < NUSERS) ? ue4 + (size_t)c * V4 : ie4 + (size_t)(c - NUSERS) * V4;
}

__global__ void k_spmm1(const float* __restrict__ ue, const float* __restrict__ ie) {
    int warp = (blockIdx.x * blockDim.x + threadIdx.x) >> 5;
    int lane = threadIdx.x & 31;
    if (warp >= NNODES) return;
    const float4* ue4 = (const float4*)ue;
    const float4* ie4 = (const float4*)ie;
    int k = g_rp[warp], e = g_rp[warp + 1];
    float4 acc = make_float4(0.f, 0.f, 0.f, 0.f);
    // peel to 16B-align the edge pair loads
    if (k < e && (k & 1)) {
        int2 ed = __ldg(&g_edge[k]);
        float v = __int_as_float(ed.y);
        const float4* x4 = feat_ptr(ed.x, ue4, ie4);
        if (lane < V4) {
            float4 xv = __ldg(&x4[lane]);
            acc.x += v * xv.x; acc.y += v * xv.y;
            acc.z += v * xv.z; acc.w += v * xv.w;
        }
        k++;
    }
    for (; k + 1 < e; k += 2) {
        int4 ep = *(const int4*)&g_edge[k];          // 2 edges, one broadcast LDG.128
        float va = __int_as_float(ep.y);
        float vb = __int_as_float(ep.w);
        const float4* xa = feat_ptr(ep.x, ue4, ie4);
        const float4* xb = feat_ptr(ep.z, ue4, ie4);
        if (lane < V4) {
            float4 A = __ldg(&xa[lane]);
            float4 B = __ldg(&xb[lane]);
            acc.x += va * A.x + vb * B.x;
            acc.y += va * A.y + vb * B.y;
            acc.z += va * A.z + vb * B.z;
            acc.w += va * A.w + vb * B.w;
        }
    }
    if (k < e) {
        int2 ed = __ldg(&g_edge[k]);
        float v = __int_as_float(ed.y);
        const float4* x4 = feat_ptr(ed.x, ue4, ie4);
        if (lane < V4) {
            float4 xv = __ldg(&x4[lane]);
            acc.x += v * xv.x; acc.y += v * xv.y;
            acc.z += v * xv.z; acc.w += v * xv.w;
        }
    }
    if (lane < V4) g_e1[(size_t)warp * V4 + lane] = acc;
}

// ====== fused tail: layer-2 gather (batch rows) + final mean + MLP ======
// 1024 threads = 32 warps: warps 0..31 gather 16 (b,side) pairs to smem,
// then warps 0..15 run the MLP (warp-per-batch-row).

constexpr int TB = 16;  // batch items per block

__global__ __launch_bounds__(1024, 1)
void k_tail(const float* __restrict__ ue, const float* __restrict__ ie,
            const int* __restrict__ uidx, const int* __restrict__ iidx,
            const float* __restrict__ W1, const float* __restrict__ b1,
            const float* __restrict__ W2, const float* __restrict__ b2,
            const float* __restrict__ W3, const float* __restrict__ b3,
            float* __restrict__ out) {
    __shared__ float W1t[100 * 64];     // 25.6 KB (half of W1 per pass)
    __shared__ float hs[TB * 200];      // 12.8 KB
    __shared__ float W2s[64 * 32];      // 8 KB
    __shared__ float b1s[64];
    __shared__ float b2s[32];
    __shared__ float W3s[32];
    __shared__ float b3s;

    int tid  = threadIdx.x;
    int w    = tid >> 5, lane = tid & 31;

    if (tid < 64) b1s[tid] = b1[tid];
    else if (tid < 96) b2s[tid - 64] = b2[tid - 64];
    else if (tid < 128) W3s[tid - 96] = W3[tid - 96];
    else if (tid == 128) b3s = b3[0];
    for (int t = tid; t < 64 * 32; t += 1024) W2s[t] = W2[t];

    // ---- gather phase: warp w handles (b_local = w>>1, side = w&1) ----
    {
        int b_local = w >> 1, side = w & 1;
        int b = blockIdx.x * TB + b_local;
        const float4* ue4 = (const float4*)ue;
        const float4* ie4 = (const float4*)ie;
        int row;
        const float4* ego4;
        if (side == 0) { int u = uidx[b]; row = u;           ego4 = ue4 + (size_t)u * V4; }
        else           { int it = iidx[b]; row = it + NUSERS; ego4 = ie4 + (size_t)it * V4; }
        int k = g_rp[row], e = g_rp[row + 1];
        float4 acc = make_float4(0.f, 0.f, 0.f, 0.f);
        if (k < e && (k & 1)) {
            int2 ed = __ldg(&g_edge[k]);
            float v = __int_as_float(ed.y);
            if (lane < V4) {
                float4 xv = g_e1[(size_t)ed.x * V4 + lane];
                acc.x += v * xv.x; acc.y += v * xv.y;
                acc.z += v * xv.z; acc.w += v * xv.w;
            }
            k++;
        }
        for (; k + 1 < e; k += 2) {
            int4 ep = *(const int4*)&g_edge[k];
            float va = __int_as_float(ep.y);
            float vb = __int_as_float(ep.w);
            if (lane < V4) {
                float4 A = g_e1[(size_t)ep.x * V4 + lane];
                float4 B = g_e1[(size_t)ep.z * V4 + lane];
                acc.x += va * A.x + vb * B.x;
                acc.y += va * A.y + vb * B.y;
                acc.z += va * A.z + vb * B.z;
                acc.w += va * A.w + vb * B.w;
            }
        }
        if (k < e) {
            int2 ed = __ldg(&g_edge[k]);
            float v = __int_as_float(ed.y);
            if (lane < V4) {
                float4 xv = g_e1[(size_t)ed.x * V4 + lane];
                acc.x += v * xv.x; acc.y += v * xv.y;
                acc.z += v * xv.z; acc.w += v * xv.w;
            }
        }
        if (lane < V4) {
            float4 eg  = __ldg(&ego4[lane]);
            float4 e1r = g_e1[(size_t)row * V4 + lane];
            const float inv3 = 1.f / 3.f;
            float4 f;
            f.x = (eg.x + e1r.x + acc.x) * inv3;
            f.y = (eg.y + e1r.y + acc.y) * inv3;
            f.z = (eg.z + e1r.z + acc.z) * inv3;
            f.w = (eg.w + e1r.w + acc.w) * inv3;
            *(float4*)&hs[b_local * 200 + side * 100 + lane * 4] = f;
        }
    }
    __syncthreads();

    // ---- MLP phase: warps 0..15, warp w -> batch row blockIdx.x*TB + w ----
    float acc0 = b1s[lane], acc1 = b1s[lane + 32];
    for (int pass = 0; pass < 2; pass++) {
        for (int t = tid; t < 100 * 64; t += 1024) W1t[t] = W1[pass * 6400 + t];
        __syncthreads();
        if (w < TB) {
            int kb = pass * 100;
#pragma unroll 4
            for (int kk = 0; kk < 100; kk++) {
                float hk = hs[w * 200 + kb + kk];
                acc0 += hk * W1t[kk * 64 + lane];
                acc1 += hk * W1t[kk * 64 + lane + 32];
            }
        }
        __syncthreads();
    }
    if (w >= TB) return;

    float h1a = fmaxf(acc0, 0.f);
    float h1b = fmaxf(acc1, 0.f);

    float acc2 = b2s[lane];
#pragma unroll
    for (int j = 0; j < 32; j++) {
        float hj = __shfl_sync(FM, h1a, j);
        acc2 += hj * W2s[j * 32 + lane];
    }
#pragma unroll
    for (int j = 0; j < 32; j++) {
        float hj = __shfl_sync(FM, h1b, j);
        acc2 += hj * W2s[(j + 32) * 32 + lane];
    }

    float p = acc2 * W3s[lane];
#pragma unroll
    for (int o = 16; o > 0; o >>= 1) p += __shfl_xor_sync(FM, p, o);
    if (lane == 0) out[blockIdx.x * TB + w] = p + b3s;
}

// ================= launch =================

extern "C" void kernel_launch(void* const* d_in, const int* in_sizes, int n_in,
                              void* d_out, int out_size) {
    const float* user_emb = (const float*)d_in[0];
    const float* item_emb = (const float*)d_in[1];
    const int*   adj_row  = (const int*)d_in[2];
    const int*   adj_col  = (const int*)d_in[3];
    const float* adj_val  = (const float*)d_in[4];
    const int*   uidx     = (const int*)d_in[5];
    const int*   iidx     = (const int*)d_in[6];
    const float* W1 = (const float*)d_in[7];
    const float* b1 = (const float*)d_in[8];
    const float* W2 = (const float*)d_in[9];
    const float* b2 = (const float*)d_in[10];
    const float* W3 = (const float*)d_in[11];
    const float* b3 = (const float*)d_in[12];
    float* out = (float*)d_out;

    void* cnt_addr = nullptr;
    cudaGetSymbolAddress(&cnt_addr, g_cntchain);
    cudaMemsetAsync(cnt_addr, 0, (NNODES + 256) * sizeof(int));

    k_hist<<<(NNZV / 4 + 255) / 256, 256>>>(adj_row);
    k_scan_fused<<<NBLK1, STILE>>>();
    k_scatter<<<(NNZV / 4 + 255) / 256, 256>>>(adj_row, adj_col, adj_val);
    k_spmm1<<<(NNODES * 32 + 255) / 256, 256>>>(user_emb, item_emb);
    k_tail<<<BATCHV / TB, 1024>>>(user_emb, item_emb, uidx, iidx,
                                  W1, b1, W2, b2, W3, b3, out);
}

// round 5
// speedup vs baseline: 1.2975x; 1.2975x over previous
#include <cuda_runtime.h>
#include <cstdint>

#define FM 0xFFFFFFFFu

constexpr int NUSERS = 100000;
constexpr int NITEMS = 50000;
constexpr int NNODES = NUSERS + NITEMS;   // 150000
constexpr int NNZV   = 2000000;
constexpr int EMBV   = 100;
constexpr int BATCHV = 16384;
constexpr int V4     = EMBV / 4;          // 25 float4 per row
constexpr int STILE  = 1024;
constexpr int NBLK1  = (NNODES + STILE - 1) / STILE; // 147

// ---- scratch (static device arrays; no runtime allocation) ----
__device__ int    g_cnt[NNODES];
__device__ int    g_scan[NNODES];
__device__ int    g_bsum[256];
__device__ int    g_rp[NNODES + 1];
__device__ int    g_cur[NNODES];
__device__ __align__(16) int2 g_edge[NNZV];          // {col, val_bits}, CSR-ordered
__device__ float4 g_e1[(size_t)NNODES * V4];         // layer-1 output, 60 MB

// ================= zero counters =================

__global__ void k_zero() {
    int i = blockIdx.x * blockDim.x + threadIdx.x;
    if (i < NNODES) g_cnt[i] = 0;
}

// ================= histogram (vectorized: 4 edges/thread) =================

__global__ void k_hist(const int* __restrict__ row) {
    int t = blockIdx.x * blockDim.x + threadIdx.x;
    int e = t * 4;
    if (e + 3 < NNZV) {
        int4 r = *(const int4*)&row[e];
        atomicAdd(&g_cnt[r.x], 1);
        atomicAdd(&g_cnt[r.y], 1);
        atomicAdd(&g_cnt[r.z], 1);
        atomicAdd(&g_cnt[r.w], 1);
    } else {
        for (int k = e; k < NNZV; k++) atomicAdd(&g_cnt[row[k]], 1);
    }
}

// ================= parallel scan (3 small kernels) =================

__global__ void k_scan1() {
    __shared__ int sm[STILE];
    int i = blockIdx.x * STILE + threadIdx.x;
    int v = (i < NNODES) ? g_cnt[i] : 0;
    sm[threadIdx.x] = v;
    __syncthreads();
    for (int off = 1; off < STILE; off <<= 1) {
        int t = (threadIdx.x >= off) ? sm[threadIdx.x - off] : 0;
        __syncthreads();
        sm[threadIdx.x] += t;
        __syncthreads();
    }
    if (i < NNODES) g_scan[i] = sm[threadIdx.x];
    if (threadIdx.x == STILE - 1) g_bsum[blockIdx.x] = sm[STILE - 1];
}

__global__ void k_scan2() {
    __shared__ int sm[256];
    int v = (threadIdx.x < NBLK1) ? g_bsum[threadIdx.x] : 0;
    sm[threadIdx.x] = v;
    __syncthreads();
    for (int off = 1; off < 256; off <<= 1) {
        int t = (threadIdx.x >= off) ? sm[threadIdx.x - off] : 0;
        __syncthreads();
        sm[threadIdx.x] += t;
        __syncthreads();
    }
    if (threadIdx.x < NBLK1) g_bsum[threadIdx.x] = sm[threadIdx.x];
}

__global__ void k_rowptr_cursor() {
    int i = blockIdx.x * blockDim.x + threadIdx.x;
    if (i < NNODES) {
        int bi   = i / STILE;
        int add  = (bi > 0) ? g_bsum[bi - 1] : 0;
        int incl = g_scan[i] + add;
        g_rp[i + 1] = incl;
        g_cur[i]    = incl - g_cnt[i];
        if (i == 0) g_rp[0] = 0;
    }
}

// ================= scatter into CSR order (4 edges/thread) =================

__global__ void k_scatter(const int* __restrict__ row, const int* __restrict__ col,
                          const float* __restrict__ val) {
    int t = blockIdx.x * blockDim.x + threadIdx.x;
    int e = t * 4;
    if (e + 3 < NNZV) {
        int4   r = *(const int4*)&row[e];
        int4   c = *(const int4*)&col[e];
        float4 v = *(const float4*)&val[e];
        int p0 = atomicAdd(&g_cur[r.x], 1); g_edge[p0] = make_int2(c.x, __float_as_int(v.x));
        int p1 = atomicAdd(&g_cur[r.y], 1); g_edge[p1] = make_int2(c.y, __float_as_int(v.y));
        int p2 = atomicAdd(&g_cur[r.z], 1); g_edge[p2] = make_int2(c.z, __float_as_int(v.z));
        int p3 = atomicAdd(&g_cur[r.w], 1); g_edge[p3] = make_int2(c.w, __float_as_int(v.w));
    } else {
        for (int k = e; k < NNZV; k++) {
            int p = atomicAdd(&g_cur[row[k]], 1);
            g_edge[p] = make_int2(col[k], __float_as_int(val[k]));
        }
    }
}

// ================= Layer 1: e1 = A @ ego (full, warp-per-row) =================

__device__ __forceinline__ const float4* feat_ptr(int c, const float4* ue4, const float4* ie4) {
    return (c < NUSERS) ? ue4 + (size_t)c * V4 : ie4 + (size_t)(c - NUSERS) * V4;
}

__global__ void k_spmm1(const float* __restrict__ ue, const float* __restrict__ ie) {
    int warp = (blockIdx.x * blockDim.x + threadIdx.x) >> 5;
    int lane = threadIdx.x & 31;
    if (warp >= NNODES) return;
    const float4* ue4 = (const float4*)ue;
    const float4* ie4 = (const float4*)ie;
    int k = g_rp[warp], e = g_rp[warp + 1];
    float4 acc = make_float4(0.f, 0.f, 0.f, 0.f);
    bool ln = (lane < V4);

    // peel to 16B-align the paired edge loads
    if (k < e && (k & 1)) {
        int2 ed = __ldg(&g_edge[k]);
        float v = __int_as_float(ed.y);
        const float4* x4 = feat_ptr(ed.x, ue4, ie4);
        if (ln) {
            float4 xv = __ldg(&x4[lane]);
            acc.x += v * xv.x; acc.y += v * xv.y;
            acc.z += v * xv.z; acc.w += v * xv.w;
        }
        k++;
    }
    // 4 edges per iteration: 2 broadcast int4 loads, 4 independent float4 loads
    for (; k + 3 < e; k += 4) {
        int4 e0 = *(const int4*)&g_edge[k];
        int4 e1 = *(const int4*)&g_edge[k + 2];
        float va = __int_as_float(e0.y), vb = __int_as_float(e0.w);
        float vc = __int_as_float(e1.y), vd = __int_as_float(e1.w);
        const float4* xa = feat_ptr(e0.x, ue4, ie4);
        const float4* xb = feat_ptr(e0.z, ue4, ie4);
        const float4* xc = feat_ptr(e1.x, ue4, ie4);
        const float4* xd = feat_ptr(e1.z, ue4, ie4);
        if (ln) {
            float4 A = __ldg(&xa[lane]);
            float4 B = __ldg(&xb[lane]);
            float4 C = __ldg(&xc[lane]);
            float4 D = __ldg(&xd[lane]);
            acc.x += va * A.x + vb * B.x + vc * C.x + vd * D.x;
            acc.y += va * A.y + vb * B.y + vc * C.y + vd * D.y;
            acc.z += va * A.z + vb * B.z + vc * C.z + vd * D.z;
            acc.w += va * A.w + vb * B.w + vc * C.w + vd * D.w;
        }
    }
    if (k + 1 < e) {
        int4 ep = *(const int4*)&g_edge[k];
        float va = __int_as_float(ep.y), vb = __int_as_float(ep.w);
        const float4* xa = feat_ptr(ep.x, ue4, ie4);
        const float4* xb = feat_ptr(ep.z, ue4, ie4);
        if (ln) {
            float4 A = __ldg(&xa[lane]);
            float4 B = __ldg(&xb[lane]);
            acc.x += va * A.x + vb * B.x;
            acc.y += va * A.y + vb * B.y;
            acc.z += va * A.z + vb * B.z;
            acc.w += va * A.w + vb * B.w;
        }
        k += 2;
    }
    if (k < e) {
        int2 ed = __ldg(&g_edge[k]);
        float v = __int_as_float(ed.y);
        const float4* x4 = feat_ptr(ed.x, ue4, ie4);
        if (ln) {
            float4 xv = __ldg(&x4[lane]);
            acc.x += v * xv.x; acc.y += v * xv.y;
            acc.z += v * xv.z; acc.w += v * xv.w;
        }
    }
    if (ln) g_e1[(size_t)warp * V4 + lane] = acc;
}

// ====== fused tail: layer-2 gather (batch rows) + final mean + MLP ======

constexpr int TB = 16;  // batch items per block

__global__ __launch_bounds__(1024, 1)
void k_tail(const float* __restrict__ ue, const float* __restrict__ ie,
            const int* __restrict__ uidx, const int* __restrict__ iidx,
            const float* __restrict__ W1, const float* __restrict__ b1,
            const float* __restrict__ W2, const float* __restrict__ b2,
            const float* __restrict__ W3, const float* __restrict__ b3,
            float* __restrict__ out) {
    __shared__ float W1t[100 * 64];     // 25.6 KB (half of W1 per pass)
    __shared__ float hs[TB * 200];      // 12.8 KB
    __shared__ float W2s[64 * 32];      // 8 KB
    __shared__ float b1s[64];
    __shared__ float b2s[32];
    __shared__ float W3s[32];
    __shared__ float b3s;

    int tid  = threadIdx.x;
    int w    = tid >> 5, lane = tid & 31;

    if (tid < 64) b1s[tid] = b1[tid];
    else if (tid < 96) b2s[tid - 64] = b2[tid - 64];
    else if (tid < 128) W3s[tid - 96] = W3[tid - 96];
    else if (tid == 128) b3s = b3[0];
    for (int t = tid; t < 64 * 32; t += 1024) W2s[t] = W2[t];

    // ---- gather phase: warp w handles (b_local = w>>1, side = w&1) ----
    {
        int b_local = w >> 1, side = w & 1;
        int b = blockIdx.x * TB + b_local;
        const float4* ue4 = (const float4*)ue;
        const float4* ie4 = (const float4*)ie;
        int row;
        const float4* ego4;
        if (side == 0) { int u = uidx[b]; row = u;           ego4 = ue4 + (size_t)u * V4; }
        else           { int it = iidx[b]; row = it + NUSERS; ego4 = ie4 + (size_t)it * V4; }
        int k = g_rp[row], e = g_rp[row + 1];
        float4 acc = make_float4(0.f, 0.f, 0.f, 0.f);
        bool ln = (lane < V4);

        if (k < e && (k & 1)) {
            int2 ed = __ldg(&g_edge[k]);
            float v = __int_as_float(ed.y);
            if (ln) {
                float4 xv = g_e1[(size_t)ed.x * V4 + lane];
                acc.x += v * xv.x; acc.y += v * xv.y;
                acc.z += v * xv.z; acc.w += v * xv.w;
            }
            k++;
        }
        for (; k + 3 < e; k += 4) {
            int4 e0 = *(const int4*)&g_edge[k];
            int4 e1 = *(const int4*)&g_edge[k + 2];
            float va = __int_as_float(e0.y), vb = __int_as_float(e0.w);
            float vc = __int_as_float(e1.y), vd = __int_as_float(e1.w);
            if (ln) {
                float4 A = g_e1[(size_t)e0.x * V4 + lane];
                float4 B = g_e1[(size_t)e0.z * V4 + lane];
                float4 C = g_e1[(size_t)e1.x * V4 + lane];
                float4 D = g_e1[(size_t)e1.z * V4 + lane];
                acc.x += va * A.x + vb * B.x + vc * C.x + vd * D.x;
                acc.y += va * A.y + vb * B.y + vc * C.y + vd * D.y;
                acc.z += va * A.z + vb * B.z + vc * C.z + vd * D.z;
                acc.w += va * A.w + vb * B.w + vc * C.w + vd * D.w;
            }
        }
        if (k + 1 < e) {
            int4 ep = *(const int4*)&g_edge[k];
            float va = __int_as_float(ep.y), vb = __int_as_float(ep.w);
            if (ln) {
                float4 A = g_e1[(size_t)ep.x * V4 + lane];
                float4 B = g_e1[(size_t)ep.z * V4 + lane];
                acc.x += va * A.x + vb * B.x;
                acc.y += va * A.y + vb * B.y;
                acc.z += va * A.z + vb * B.z;
                acc.w += va * A.w + vb * B.w;
            }
            k += 2;
        }
        if (k < e) {
            int2 ed = __ldg(&g_edge[k]);
            float v = __int_as_float(ed.y);
            if (ln) {
                float4 xv = g_e1[(size_t)ed.x * V4 + lane];
                acc.x += v * xv.x; acc.y += v * xv.y;
                acc.z += v * xv.z; acc.w += v * xv.w;
            }
        }
        if (ln) {
            float4 eg  = __ldg(&ego4[lane]);
            float4 e1r = g_e1[(size_t)row * V4 + lane];
            const float inv3 = 1.f / 3.f;
            float4 f;
            f.x = (eg.x + e1r.x + acc.x) * inv3;
            f.y = (eg.y + e1r.y + acc.y) * inv3;
            f.z = (eg.z + e1r.z + acc.z) * inv3;
            f.w = (eg.w + e1r.w + acc.w) * inv3;
            *(float4*)&hs[b_local * 200 + side * 100 + lane * 4] = f;
        }
    }
    __syncthreads();

    // ---- MLP phase: warps 0..15, warp w -> batch row blockIdx.x*TB + w ----
    float acc0 = b1s[lane], acc1 = b1s[lane + 32];
    for (int pass = 0; pass < 2; pass++) {
        for (int t = tid; t < 100 * 64; t += 1024) W1t[t] = W1[pass * 6400 + t];
        __syncthreads();
        if (w < TB) {
            int kb = pass * 100;
#pragma unroll 4
            for (int kk = 0; kk < 100; kk++) {
                float hk = hs[w * 200 + kb + kk];
                acc0 += hk * W1t[kk * 64 + lane];
                acc1 += hk * W1t[kk * 64 + lane + 32];
            }
        }
        __syncthreads();
    }
    if (w >= TB) return;

    float h1a = fmaxf(acc0, 0.f);
    float h1b = fmaxf(acc1, 0.f);

    float acc2 = b2s[lane];
#pragma unroll
    for (int j = 0; j < 32; j++) {
        float hj = __shfl_sync(FM, h1a, j);
        acc2 += hj * W2s[j * 32 + lane];
    }
#pragma unroll
    for (int j = 0; j < 32; j++) {
        float hj = __shfl_sync(FM, h1b, j);
        acc2 += hj * W2s[(j + 32) * 32 + lane];
    }

    float p = acc2 * W3s[lane];
#pragma unroll
    for (int o = 16; o > 0; o >>= 1) p += __shfl_xor_sync(FM, p, o);
    if (lane == 0) out[blockIdx.x * TB + w] = p + b3s;
}

// ================= launch =================

extern "C" void kernel_launch(void* const* d_in, const int* in_sizes, int n_in,
                              void* d_out, int out_size) {
    const float* user_emb = (const float*)d_in[0];
    const float* item_emb = (const float*)d_in[1];
    const int*   adj_row  = (const int*)d_in[2];
    const int*   adj_col  = (const int*)d_in[3];
    const float* adj_val  = (const float*)d_in[4];
    const int*   uidx     = (const int*)d_in[5];
    const int*   iidx     = (const int*)d_in[6];
    const float* W1 = (const float*)d_in[7];
    const float* b1 = (const float*)d_in[8];
    const float* W2 = (const float*)d_in[9];
    const float* b2 = (const float*)d_in[10];
    const float* W3 = (const float*)d_in[11];
    const float* b3 = (const float*)d_in[12];
    float* out = (float*)d_out;

    k_zero<<<(NNODES + 255) / 256, 256>>>();
    k_hist<<<(NNZV / 4 + 255) / 256, 256>>>(adj_row);
    k_scan1<<<NBLK1, STILE>>>();
    k_scan2<<<1, 256>>>();
    k_rowptr_cursor<<<(NNODES + 255) / 256, 256>>>();
    k_scatter<<<(NNZV / 4 + 255) / 256, 256>>>(adj_row, adj_col, adj_val);
    k_spmm1<<<(NNODES * 32 + 255) / 256, 256>>>(user_emb, item_emb);
    k_tail<<<BATCHV / TB, 1024>>>(user_emb, item_emb, uidx, iidx,
                                  W1, b1, W2, b2, W3, b3, out);
}